// round 14
// baseline (speedup 1.0000x reference)
#include <cuda_runtime.h>
#include <cuda_fp16.h>
#include <math.h>
#include <stdint.h>
#include <string.h>

// ---------------------------------------------------------------------------
// Problem constants
// ---------------------------------------------------------------------------
#define BB 16
#define LL 4096
#define HH 512
#define PP 256
#define MM (BB * LL)          // 65536 rows
#define KK 512                // GEMM K
#define CH 128                // scan chunk length
#define NCHUNK (LL / CH)      // 32
#define LN_EPS 1e-6f

// GEMM tiling
#define BM 128
#define BN 128
#define BK 32
#define NIT (KK / BK)         // 16
#define BKP 40                // A smem k-stride (halves)
#define BNP 136               // B smem n-stride (halves)
// 4-stage smem layout
#define SA_BYTES 10240        // 128*40*2
#define SB_BYTES 8704         // 32*136*2
#define STG_BYTES (SA_BYTES + SB_BYTES)   // 18944
#define NSTG 4
#define SM_BYTES (NSTG * STG_BYTES)       // 75776 >= 33792 (C tile reuse)
#define CT_STRIDE 66          // half2 per row (132 halves)
#define NROWBLK (MM / BM)     // 512
#define NCHAIN (NROWBLK * 4)  // 2048 lookback slots (per by per bx)

// ---------------------------------------------------------------------------
// Scratch (static __device__)
// Interleaved complex: col 2p = re, col 2p+1 = im.
// ---------------------------------------------------------------------------
__device__ __half g_XS[(size_t)MM * KK];   // xs (written directly by GEMM1)
__device__ __half g_ysh[(size_t)MM * HH];
__device__ __half g_W1[KK * HH];
__device__ __half g_W2[KK * HH];
__device__ float g_lbar[2 * PP];
__device__ float g_a32[2 * PP];    // lbar^32
__device__ float g_aC[2 * PP];     // lbar^128
__device__ float g_incl[NCHAIN * 128];   // inclusive chunk prefixes (64 p x re/im)
__device__ int   g_flag[NCHAIN];         // publish flags (reset each launch)
__device__ int   g_cnt[NROWBLK];         // epilogue counters (reset each launch)

// ---------------------------------------------------------------------------
// PTX helpers
// ---------------------------------------------------------------------------
__device__ __forceinline__ uint32_t s2u(const void* p) {
    return (uint32_t)__cvta_generic_to_shared(p);
}
__device__ __forceinline__ void ldsm4(uint32_t* r, uint32_t a) {
    asm volatile("ldmatrix.sync.aligned.m8n8.x4.shared.b16 {%0,%1,%2,%3},[%4];\n"
                 : "=r"(r[0]), "=r"(r[1]), "=r"(r[2]), "=r"(r[3]) : "r"(a));
}
__device__ __forceinline__ void ldsm4t(uint32_t* r, uint32_t a) {
    asm volatile("ldmatrix.sync.aligned.m8n8.x4.trans.shared.b16 {%0,%1,%2,%3},[%4];\n"
                 : "=r"(r[0]), "=r"(r[1]), "=r"(r[2]), "=r"(r[3]) : "r"(a));
}
__device__ __forceinline__ void mma16816(float* d, const uint32_t* a, uint32_t b0, uint32_t b1) {
    asm volatile("mma.sync.aligned.m16n8k16.row.col.f32.f16.f16.f32 "
                 "{%0,%1,%2,%3},{%4,%5,%6,%7},{%8,%9},{%0,%1,%2,%3};\n"
                 : "+f"(d[0]), "+f"(d[1]), "+f"(d[2]), "+f"(d[3])
                 : "r"(a[0]), "r"(a[1]), "r"(a[2]), "r"(a[3]), "r"(b0), "r"(b1));
}
__device__ __forceinline__ void cp16(uint32_t dst, const void* src) {
    asm volatile("cp.async.cg.shared.global [%0], [%1], 16;" :: "r"(dst), "l"(src));
}
__device__ __forceinline__ void cp_commit() {
    asm volatile("cp.async.commit_group;" ::: "memory");
}
__device__ __forceinline__ void cp_wait2() {
    asm volatile("cp.async.wait_group 2;" ::: "memory");
}
__device__ __forceinline__ void cp_wait1() {
    asm volatile("cp.async.wait_group 1;" ::: "memory");
}
__device__ __forceinline__ void cp_wait0() {
    asm volatile("cp.async.wait_group 0;" ::: "memory");
}

// ---------------------------------------------------------------------------
// Shared per-p math
// ---------------------------------------------------------------------------
__device__ __forceinline__ void lambda_math(float llr, float lim, float lst,
                                            float& lbr, float& lbi,
                                            float& cr, float& ci) {
    float lam_re = -expf(llr);
    float lam_im = lim;
    float st = expf(lst);
    float ar = lam_re * st, ai = lam_im * st;
    float e = expf(ar);
    lbr = e * cosf(ai);
    lbi = e * sinf(ai);
    float nr = lbr - 1.0f, ni = lbi;
    float d2 = lam_re * lam_re + lam_im * lam_im;
    cr = (nr * lam_re + ni * lam_im) / d2;
    ci = (ni * lam_re - nr * lam_im) / d2;
}

// ---------------------------------------------------------------------------
// Merged setup: block 0 writes scalar tables and resets ALL flags/counters;
// other blocks build W1/W2.
// ---------------------------------------------------------------------------
__global__ void k_setup_all(const float* __restrict__ log_lambda_re,
                            const float* __restrict__ lambda_im,
                            const float* __restrict__ log_step,
                            const float* __restrict__ B_re,
                            const float* __restrict__ B_im,
                            const float* __restrict__ C_re,
                            const float* __restrict__ C_im) {
    if (blockIdx.x == 0) {
        int p = threadIdx.x;
        // reset epilogue counters (512) and lookback flags (2048)
        g_cnt[p] = 0;
        g_cnt[p + 256] = 0;
        #pragma unroll
        for (int i = 0; i < 8; i++) g_flag[p + 256 * i] = 0;
        if (p < PP) {
            float lbr, lbi, cr, ci;
            lambda_math(log_lambda_re[p], lambda_im[p], log_step[p], lbr, lbi, cr, ci);
            g_lbar[p] = lbr; g_lbar[PP + p] = lbi;
            float sr = lbr, si = lbi;
            #pragma unroll
            for (int i = 0; i < 5; i++) {      // ^32
                float r2 = sr * sr - si * si;
                float i2 = 2.0f * sr * si;
                sr = r2; si = i2;
            }
            g_a32[p] = sr; g_a32[PP + p] = si;
            #pragma unroll
            for (int i = 0; i < 2; i++) {      // ^128
                float r2 = sr * sr - si * si;
                float i2 = 2.0f * sr * si;
                sr = r2; si = i2;
            }
            g_aC[p] = sr; g_aC[PP + p] = si;
        }
        return;
    }
    int idx = (blockIdx.x - 1) * blockDim.x + threadIdx.x;
    if (idx >= PP * HH) return;
    int p = idx / HH;
    int h = idx % HH;
    float lbr, lbi, cr, ci;
    lambda_math(log_lambda_re[p], lambda_im[p], log_step[p], lbr, lbi, cr, ci);
    float br = B_re[p * HH + h], bi = B_im[p * HH + h];
    float w1r = cr * br - ci * bi;
    float w1i = cr * bi + ci * br;
    g_W1[h * KK + 2 * p]     = __float2half_rn(w1r);
    g_W1[h * KK + 2 * p + 1] = __float2half_rn(w1i);
    g_W2[(2 * p) * HH + h]     = __float2half_rn( 2.0f * C_re[h * PP + p]);
    g_W2[(2 * p + 1) * HH + h] = __float2half_rn(-2.0f * C_im[h * PP + p]);
}

// ---------------------------------------------------------------------------
// 4-stage pipelined fp16 GEMM, 2 CTAs/SM.
// CONV:  A fp32 via LDG->regs->deferred STS.  !CONV: A fp16 via cp.async.
// FUSE_SCAN (GEMM1): keep C tile in smem, decoupled-lookback chunk scan,
//                    write xs directly (no Bu round-trip).
// FUSE_E (GEMM2): last CTA of each row block runs gelu+residual+LayerNorm.
// ---------------------------------------------------------------------------
template <bool CONV, bool FUSE_SCAN, bool FUSE_E>
__global__ __launch_bounds__(256, 2) void k_gemm_f16(
    const float* __restrict__ Af,
    const __half* __restrict__ Ah,
    const __half* __restrict__ W,
    __half* __restrict__ C,
    const float* __restrict__ Xf,
    const float* __restrict__ Dv,
    const float* __restrict__ ln_scale,
    const float* __restrict__ ln_bias,
    float* __restrict__ out)
{
    __shared__ __align__(16) char sm[SM_BYTES];
    __shared__ float2 s_part[4][64];
    __shared__ float2 s_seed[64];
    __shared__ int s_go;

    uint32_t smb = s2u(sm);
    int tid = threadIdx.x;
    int bx = blockIdx.x, by = blockIdx.y;
    int lane = tid & 31, wid = tid >> 5;
    int wm = (wid & 1) * 64;
    int wn = (wid >> 1) * 32;

    int a_r = lane & 15;
    int a_c = (lane >> 4) * 8;
    int b_r = (lane & 7) + ((lane >> 3) & 1) * 8;
    int b_c = (lane >> 4) * 8;

    float acc[4][4][4];
    #pragma unroll
    for (int i = 0; i < 4; i++)
        #pragma unroll
        for (int j = 0; j < 4; j++)
            #pragma unroll
            for (int c = 0; c < 4; c++) acc[i][j][c] = 0.0f;

    int af_row = tid >> 3, af_col = (tid & 7) * 4;
    float4 areg[4];

    auto sA = [&](int st) { return smb + st * STG_BYTES; };
    auto sB = [&](int st) { return smb + st * STG_BYTES + SA_BYTES; };

    auto cpB = [&](int it, int st) {
        uint32_t base = sB(st);
        #pragma unroll
        for (int i = 0; i < 2; i++) {
            int cidx = tid + 256 * i;
            int row = cidx >> 4;
            int c16 = cidx & 15;
            cp16(base + row * 272 + c16 * 16,
                 W + (size_t)(it * BK + row) * 512 + bx * BN + c16 * 8);
        }
    };
    auto cpA = [&](int it, int st) {
        uint32_t base = sA(st);
        #pragma unroll
        for (int i = 0; i < 2; i++) {
            int cidx = tid + 256 * i;
            int row = cidx >> 2;
            int c16 = cidx & 3;
            cp16(base + row * 80 + c16 * 16,
                 Ah + (size_t)(by * BM + row) * 512 + it * BK + c16 * 8);
        }
    };
    auto ldgA = [&](int it) {
        #pragma unroll
        for (int r = 0; r < 4; r++)
            areg[r] = *reinterpret_cast<const float4*>(
                Af + (size_t)(by * BM + af_row + r * 32) * 512 + it * BK + af_col);
    };
    auto stsA = [&](int st) {
        uint32_t base = sA(st);
        #pragma unroll
        for (int r = 0; r < 4; r++) {
            float4 v = areg[r];
            __half2 h0 = __floats2half2_rn(v.x, v.y);
            __half2 h1 = __floats2half2_rn(v.z, v.w);
            uint32_t u0, u1;
            memcpy(&u0, &h0, 4); memcpy(&u1, &h1, 4);
            asm volatile("st.shared.v2.b32 [%0], {%1, %2};"
                :: "r"(base + ((af_row + r * 32) * BKP + af_col) * 2), "r"(u0), "r"(u1)
                : "memory");
        }
    };

    // prologue: stages 0,1,2
    #pragma unroll
    for (int s = 0; s < 3; s++) {
        cpB(s, s);
        if (CONV) { ldgA(s); stsA(s); } else cpA(s, s);
        cp_commit();
    }

    for (int it = 0; it < NIT; it++) {
        int st = it & 3;
        if (it < NIT - 2) cp_wait2();
        else if (it == NIT - 2) cp_wait1();
        else cp_wait0();
        __syncthreads();
        bool pf = (it + 3 < NIT);
        if (pf) {
            int st2 = (it + 3) & 3;
            cpB(it + 3, st2);
            if (CONV) ldgA(it + 3);
            else cpA(it + 3, st2);
            cp_commit();
        }

        uint32_t a_base = sA(st), b_base = sB(st);
        #pragma unroll
        for (int ks = 0; ks < BK; ks += 16) {
            uint32_t bf[2][4];
            #pragma unroll
            for (int j2 = 0; j2 < 2; j2++)
                ldsm4t(bf[j2], b_base + ((ks + b_r) * BNP + wn + j2 * 16 + b_c) * 2);
            #pragma unroll
            for (int i = 0; i < 4; i++) {
                uint32_t a[4];
                ldsm4(a, a_base + ((wm + i * 16 + a_r) * BKP + ks + a_c) * 2);
                #pragma unroll
                for (int j = 0; j < 4; j++)
                    mma16816(acc[i][j], a, bf[j >> 1][(j & 1) * 2], bf[j >> 1][(j & 1) * 2 + 1]);
            }
        }
        if (pf && CONV) stsA((it + 3) & 3);
    }

    if (FUSE_SCAN) __syncthreads();   // done with stage smem before C-tile reuse
    __half2* Ct = reinterpret_cast<__half2*>(sm);

    // --- store C: gmem for plain/FUSE_E; smem tile only for FUSE_SCAN ---
    #pragma unroll
    for (int i = 0; i < 4; i++) {
        int rl0 = wm + i * 16 + (lane >> 2);
        int r0 = by * BM + rl0;
        int cl0 = wn + (lane & 3) * 2;
        int c0 = bx * BN + cl0;
        #pragma unroll
        for (int j = 0; j < 4; j++) {
            __half2 v0 = __floats2half2_rn(acc[i][j][0], acc[i][j][1]);
            __half2 v1 = __floats2half2_rn(acc[i][j][2], acc[i][j][3]);
            if (FUSE_SCAN) {
                Ct[rl0 * CT_STRIDE + ((cl0 + j * 8) >> 1)] = v0;
                Ct[(rl0 + 8) * CT_STRIDE + ((cl0 + j * 8) >> 1)] = v1;
            } else {
                *reinterpret_cast<__half2*>(&C[(size_t)r0 * 512 + c0 + j * 8]) = v0;
                *reinterpret_cast<__half2*>(&C[(size_t)(r0 + 8) * 512 + c0 + j * 8]) = v1;
            }
        }
    }

    if (FUSE_SCAN) {
        __syncthreads();
        // segment carries over the smem tile (4 segs x 64 p-cols)
        int seg = tid >> 6;
        int pl = tid & 63;
        int pg = bx * 64 + pl;
        {
            float ar = g_lbar[pg], ai = g_lbar[PP + pg];
            float sr = 0.0f, si = 0.0f;
            int t0 = seg * 32;
            #pragma unroll 4
            for (int t = t0; t < t0 + 32; t++) {
                float2 v = __half22float2(Ct[t * CT_STRIDE + pl]);
                float nr = fmaf(ar, sr, fmaf(-ai, si, v.x));
                float ni = fmaf(ar, si, fmaf(ai, sr, v.y));
                sr = nr; si = ni;
            }
            s_part[seg][pl] = make_float2(sr, si);
        }
        __syncthreads();

        // lookback: combine segments, wait predecessor, publish inclusive
        int jj = by & (NCHUNK - 1);           // chunk index within batch
        int slot = by * 4 + bx;
        if (tid < 64) {
            int pg2 = bx * 64 + tid;
            float a32r = g_a32[pg2], a32i = g_a32[PP + pg2];
            float2 c = s_part[0][tid];
            #pragma unroll
            for (int k = 1; k < 4; k++) {
                float2 pk = s_part[k][tid];
                float cr = a32r * c.x - a32i * c.y + pk.x;
                float ci = a32r * c.y + a32i * c.x + pk.y;
                c.x = cr; c.y = ci;
            }
            float2 prev = make_float2(0.0f, 0.0f);
            if (jj > 0) {
                volatile int* fl = &g_flag[slot - 4];
                while (*fl == 0) { }
                __threadfence();
                volatile float* ip = &g_incl[(size_t)(slot - 4) * 128 + tid * 2];
                prev.x = ip[0];
                prev.y = ip[1];
            }
            s_seed[tid] = prev;
            float a128r = g_aC[pg2], a128i = g_aC[PP + pg2];
            float ir = a128r * prev.x - a128i * prev.y + c.x;
            float ii = a128r * prev.y + a128i * prev.x + c.y;
            g_incl[(size_t)slot * 128 + tid * 2]     = ir;
            g_incl[(size_t)slot * 128 + tid * 2 + 1] = ii;
        }
        __syncthreads();
        if (tid == 0) {
            __threadfence();
            atomicExch(&g_flag[slot], 1);
        }

        // apply recurrence seeded with exclusive prefix; write xs directly
        {
            float2 st = s_seed[pl];
            float a32r = g_a32[pg], a32i = g_a32[PP + pg];
            #pragma unroll
            for (int k = 0; k < 3; k++) {
                if (k < seg) {
                    float2 pk = s_part[k][pl];
                    float nr = a32r * st.x - a32i * st.y + pk.x;
                    float ni = a32r * st.y + a32i * st.x + pk.y;
                    st.x = nr; st.y = ni;
                }
            }
            float lr = g_lbar[pg], li = g_lbar[PP + pg];
            __half2* xs = reinterpret_cast<__half2*>(C);
            size_t base = (size_t)by * BM * PP + pg;
            int t0 = seg * 32;
            #pragma unroll 4
            for (int t = t0; t < t0 + 32; t++) {
                float2 v = __half22float2(Ct[t * CT_STRIDE + pl]);
                float nr = fmaf(lr, st.x, fmaf(-li, st.y, v.x));
                float ni = fmaf(lr, st.y, fmaf(li, st.x, v.y));
                st.x = nr; st.y = ni;
                xs[base + (size_t)t * PP] = __floats2half2_rn(st.x, st.y);
            }
        }
    }

    if (FUSE_E) {
        // last CTA of this 128-row block runs the full epilogue (L2-hot ys)
        __threadfence();
        if (tid == 0) s_go = (atomicAdd(&g_cnt[by], 1) == 3) ? 1 : 0;
        __syncthreads();
        if (s_go) {
            for (int r = wid; r < BM; r += 8) {
                int row = by * BM + r;
                const __half* ysr = C + (size_t)row * 512;
                const float* xr = Xf + (size_t)row * 512;
                float zv[16];
                float sum = 0.0f, sum2 = 0.0f;
                #pragma unroll
                for (int q = 0; q < 16; q++) {
                    int cc = lane + 32 * q;
                    float ys = __half2float(ysr[cc]);
                    float xv = xr[cc];
                    float y = ys + xv * Dv[cc];
                    float y3 = y * y * y;
                    float u = 0.7978845608028654f * (y + 0.044715f * y3);
                    float g = 0.5f * y * (1.0f + tanhf(u));
                    float z = xv + g;
                    zv[q] = z;
                    sum += z; sum2 += z * z;
                }
                #pragma unroll
                for (int off = 16; off > 0; off >>= 1) {
                    sum  += __shfl_xor_sync(0xFFFFFFFFu, sum, off);
                    sum2 += __shfl_xor_sync(0xFFFFFFFFu, sum2, off);
                }
                float mean = sum * (1.0f / HH);
                float var = sum2 * (1.0f / HH) - mean * mean;
                float rstd = rsqrtf(var + LN_EPS);
                float* outr = out + (size_t)row * 512;
                #pragma unroll
                for (int q = 0; q < 16; q++) {
                    int cc = lane + 32 * q;
                    outr[cc] = (zv[q] - mean) * rstd * ln_scale[cc] + ln_bias[cc];
                }
            }
        }
    }
}

// ---------------------------------------------------------------------------
// Launch
// ---------------------------------------------------------------------------
extern "C" void kernel_launch(void* const* d_in, const int* in_sizes, int n_in,
                              void* d_out, int out_size) {
    const float* x             = (const float*)d_in[0];
    const float* log_lambda_re = (const float*)d_in[1];
    const float* lambda_im     = (const float*)d_in[2];
    const float* B_re          = (const float*)d_in[3];
    const float* B_im          = (const float*)d_in[4];
    const float* C_re          = (const float*)d_in[5];
    const float* C_im          = (const float*)d_in[6];
    const float* D             = (const float*)d_in[7];
    const float* log_step      = (const float*)d_in[8];
    const float* ln_scale      = (const float*)d_in[9];
    const float* ln_bias       = (const float*)d_in[10];
    float* out = (float*)d_out;

    // merged setup: block 0 = scalars + flag/counter reset, blocks 1.. = weights
    k_setup_all<<<1 + (PP * HH + 255) / 256, 256>>>(
        log_lambda_re, lambda_im, log_step, B_re, B_im, C_re, C_im);

    __half *gXS, *gYS, *gW1, *gW2;
    cudaGetSymbolAddress((void**)&gXS, g_XS);
    cudaGetSymbolAddress((void**)&gYS, g_ysh);
    cudaGetSymbolAddress((void**)&gW1, g_W1);
    cudaGetSymbolAddress((void**)&gW2, g_W2);

    dim3 grid(HH / BN, MM / BM);   // (4, 512)

    // GEMM1: xs = scan(x @ W1) — fused decoupled-lookback scan, writes xs
    k_gemm_f16<true, true, false><<<grid, 256>>>(
        x, nullptr, gW1, gXS, nullptr, nullptr, nullptr, nullptr, nullptr);

    // GEMM2: ys = xs @ W2 (fp16 A via cp.async) + fused LN epilogue
    k_gemm_f16<false, false, true><<<grid, 256>>>(
        nullptr, gXS, gW2, gYS, x, D, ln_scale, ln_bias, out);
}

// round 15
// speedup vs baseline: 1.4497x; 1.4497x over previous
#include <cuda_runtime.h>
#include <cuda_fp16.h>
#include <math.h>
#include <stdint.h>
#include <string.h>

// ---------------------------------------------------------------------------
// Problem constants
// ---------------------------------------------------------------------------
#define BB 16
#define LL 4096
#define HH 512
#define PP 256
#define MM (BB * LL)          // 65536 rows
#define KK 512                // GEMM K
#define CH 128                // scan chunk length
#define NCHUNK (LL / CH)      // 32
#define LN_EPS 1e-6f

// GEMM tiling
#define BM 128
#define BN 128
#define BK 32
#define NIT (KK / BK)         // 16
#define BKP 40                // A smem k-stride (halves)
#define BNP 136               // B smem n-stride (halves)
// 4-stage smem layout
#define SA_BYTES 10240        // 128*40*2
#define SB_BYTES 8704         // 32*136*2
#define STG_BYTES (SA_BYTES + SB_BYTES)   // 18944
#define NSTG 4
#define SM_BYTES (NSTG * STG_BYTES)       // 75776 >= 33792 (C tile reuse)
#define CT_STRIDE 66          // half2 per row (132 halves)
#define NROWBLK (MM / BM)     // 512
#define NCHAIN (NROWBLK * 4)  // 2048 lookback slots

// ---------------------------------------------------------------------------
// Scratch (static __device__)
// Interleaved complex: col 2p = re, col 2p+1 = im.
// ---------------------------------------------------------------------------
__device__ __half g_XS[(size_t)MM * KK];   // xs (written directly by GEMM1)
__device__ __half g_ysh[(size_t)MM * HH];
__device__ __half g_W1[KK * HH];
__device__ __half g_W2[KK * HH];
__device__ float g_lbar[2 * PP];
__device__ float g_a32[2 * PP];    // lbar^32
__device__ float g_aC[2 * PP];     // lbar^128
__device__ float g_incl[NCHAIN * 128];   // inclusive chunk prefixes
__device__ int   g_flag[NCHAIN];         // publish flags (reset each launch)
__device__ int   g_cnt[NROWBLK];         // epilogue counters (reset each launch)

// ---------------------------------------------------------------------------
// PTX helpers
// ---------------------------------------------------------------------------
__device__ __forceinline__ uint32_t s2u(const void* p) {
    return (uint32_t)__cvta_generic_to_shared(p);
}
__device__ __forceinline__ void ldsm4(uint32_t* r, uint32_t a) {
    asm volatile("ldmatrix.sync.aligned.m8n8.x4.shared.b16 {%0,%1,%2,%3},[%4];\n"
                 : "=r"(r[0]), "=r"(r[1]), "=r"(r[2]), "=r"(r[3]) : "r"(a));
}
__device__ __forceinline__ void ldsm4t(uint32_t* r, uint32_t a) {
    asm volatile("ldmatrix.sync.aligned.m8n8.x4.trans.shared.b16 {%0,%1,%2,%3},[%4];\n"
                 : "=r"(r[0]), "=r"(r[1]), "=r"(r[2]), "=r"(r[3]) : "r"(a));
}
__device__ __forceinline__ void mma16816(float* d, const uint32_t* a, uint32_t b0, uint32_t b1) {
    asm volatile("mma.sync.aligned.m16n8k16.row.col.f32.f16.f16.f32 "
                 "{%0,%1,%2,%3},{%4,%5,%6,%7},{%8,%9},{%0,%1,%2,%3};\n"
                 : "+f"(d[0]), "+f"(d[1]), "+f"(d[2]), "+f"(d[3])
                 : "r"(a[0]), "r"(a[1]), "r"(a[2]), "r"(a[3]), "r"(b0), "r"(b1));
}
__device__ __forceinline__ void cp16(uint32_t dst, const void* src) {
    asm volatile("cp.async.cg.shared.global [%0], [%1], 16;" :: "r"(dst), "l"(src));
}
__device__ __forceinline__ void cp_commit() {
    asm volatile("cp.async.commit_group;" ::: "memory");
}
__device__ __forceinline__ void cp_wait2() {
    asm volatile("cp.async.wait_group 2;" ::: "memory");
}
__device__ __forceinline__ void cp_wait1() {
    asm volatile("cp.async.wait_group 1;" ::: "memory");
}
__device__ __forceinline__ void cp_wait0() {
    asm volatile("cp.async.wait_group 0;" ::: "memory");
}

// ---------------------------------------------------------------------------
// Shared per-p math
// ---------------------------------------------------------------------------
__device__ __forceinline__ void lambda_math(float llr, float lim, float lst,
                                            float& lbr, float& lbi,
                                            float& cr, float& ci) {
    float lam_re = -expf(llr);
    float lam_im = lim;
    float st = expf(lst);
    float ar = lam_re * st, ai = lam_im * st;
    float e = expf(ar);
    lbr = e * cosf(ai);
    lbi = e * sinf(ai);
    float nr = lbr - 1.0f, ni = lbi;
    float d2 = lam_re * lam_re + lam_im * lam_im;
    cr = (nr * lam_re + ni * lam_im) / d2;
    ci = (ni * lam_re - nr * lam_im) / d2;
}

// ---------------------------------------------------------------------------
// Merged setup: block 0 writes scalar tables and resets ALL flags/counters;
// other blocks build W1/W2.
// ---------------------------------------------------------------------------
__global__ void k_setup_all(const float* __restrict__ log_lambda_re,
                            const float* __restrict__ lambda_im,
                            const float* __restrict__ log_step,
                            const float* __restrict__ B_re,
                            const float* __restrict__ B_im,
                            const float* __restrict__ C_re,
                            const float* __restrict__ C_im) {
    if (blockIdx.x == 0) {
        int p = threadIdx.x;
        g_cnt[p] = 0;
        g_cnt[p + 256] = 0;
        #pragma unroll
        for (int i = 0; i < 8; i++) g_flag[p + 256 * i] = 0;
        if (p < PP) {
            float lbr, lbi, cr, ci;
            lambda_math(log_lambda_re[p], lambda_im[p], log_step[p], lbr, lbi, cr, ci);
            g_lbar[p] = lbr; g_lbar[PP + p] = lbi;
            float sr = lbr, si = lbi;
            #pragma unroll
            for (int i = 0; i < 5; i++) {      // ^32
                float r2 = sr * sr - si * si;
                float i2 = 2.0f * sr * si;
                sr = r2; si = i2;
            }
            g_a32[p] = sr; g_a32[PP + p] = si;
            #pragma unroll
            for (int i = 0; i < 2; i++) {      // ^128
                float r2 = sr * sr - si * si;
                float i2 = 2.0f * sr * si;
                sr = r2; si = i2;
            }
            g_aC[p] = sr; g_aC[PP + p] = si;
        }
        return;
    }
    int idx = (blockIdx.x - 1) * blockDim.x + threadIdx.x;
    if (idx >= PP * HH) return;
    int p = idx / HH;
    int h = idx % HH;
    float lbr, lbi, cr, ci;
    lambda_math(log_lambda_re[p], lambda_im[p], log_step[p], lbr, lbi, cr, ci);
    float br = B_re[p * HH + h], bi = B_im[p * HH + h];
    float w1r = cr * br - ci * bi;
    float w1i = cr * bi + ci * br;
    g_W1[h * KK + 2 * p]     = __float2half_rn(w1r);
    g_W1[h * KK + 2 * p + 1] = __float2half_rn(w1i);
    g_W2[(2 * p) * HH + h]     = __float2half_rn( 2.0f * C_re[h * PP + p]);
    g_W2[(2 * p + 1) * HH + h] = __float2half_rn(-2.0f * C_im[h * PP + p]);
}

// ---------------------------------------------------------------------------
// 4-stage pipelined fp16 GEMM, 2 CTAs/SM.
// CONV:  A fp32 via LDG->regs->deferred STS.  !CONV: A fp16 via cp.async.
// FUSE_SCAN (GEMM1): C tile stays in smem; decoupled-lookback scan with
//   wave-spread chain links (by remap) and polite single-thread spin;
//   writes xs directly (no Bu round-trip).
// FUSE_E (GEMM2): last CTA of each row block runs gelu+residual+LayerNorm.
// ---------------------------------------------------------------------------
template <bool CONV, bool FUSE_SCAN, bool FUSE_E>
__global__ __launch_bounds__(256, 2) void k_gemm_f16(
    const float* __restrict__ Af,
    const __half* __restrict__ Ah,
    const __half* __restrict__ W,
    __half* __restrict__ C,
    const float* __restrict__ Xf,
    const float* __restrict__ Dv,
    const float* __restrict__ ln_scale,
    const float* __restrict__ ln_bias,
    float* __restrict__ out)
{
    __shared__ __align__(16) char sm[SM_BYTES];
    __shared__ float2 s_part[4][64];
    __shared__ float2 s_seed[64];
    __shared__ int s_go;

    uint32_t smb = s2u(sm);
    int tid = threadIdx.x;
    int bx = blockIdx.x;
    // Wave-spread remap for the scan-fused GEMM: chain links (chunk j, j-1 of
    // the same batch) land 64 linear block-IDs apart instead of 4, so the
    // 32-deep ripple spreads across waves instead of serializing one wave.
    int by;
    if (FUSE_SCAN) {
        int byr = blockIdx.y;
        by = ((byr & 15) << 5) | (byr >> 4);   // b*32 + j
    } else {
        by = blockIdx.y;
    }
    int lane = tid & 31, wid = tid >> 5;
    int wm = (wid & 1) * 64;
    int wn = (wid >> 1) * 32;

    int a_r = lane & 15;
    int a_c = (lane >> 4) * 8;
    int b_r = (lane & 7) + ((lane >> 3) & 1) * 8;
    int b_c = (lane >> 4) * 8;

    float acc[4][4][4];
    #pragma unroll
    for (int i = 0; i < 4; i++)
        #pragma unroll
        for (int j = 0; j < 4; j++)
            #pragma unroll
            for (int c = 0; c < 4; c++) acc[i][j][c] = 0.0f;

    int af_row = tid >> 3, af_col = (tid & 7) * 4;
    float4 areg[4];

    auto sA = [&](int st) { return smb + st * STG_BYTES; };
    auto sB = [&](int st) { return smb + st * STG_BYTES + SA_BYTES; };

    auto cpB = [&](int it, int st) {
        uint32_t base = sB(st);
        #pragma unroll
        for (int i = 0; i < 2; i++) {
            int cidx = tid + 256 * i;
            int row = cidx >> 4;
            int c16 = cidx & 15;
            cp16(base + row * 272 + c16 * 16,
                 W + (size_t)(it * BK + row) * 512 + bx * BN + c16 * 8);
        }
    };
    auto cpA = [&](int it, int st) {
        uint32_t base = sA(st);
        #pragma unroll
        for (int i = 0; i < 2; i++) {
            int cidx = tid + 256 * i;
            int row = cidx >> 2;
            int c16 = cidx & 3;
            cp16(base + row * 80 + c16 * 16,
                 Ah + (size_t)(by * BM + row) * 512 + it * BK + c16 * 8);
        }
    };
    auto ldgA = [&](int it) {
        #pragma unroll
        for (int r = 0; r < 4; r++)
            areg[r] = *reinterpret_cast<const float4*>(
                Af + (size_t)(by * BM + af_row + r * 32) * 512 + it * BK + af_col);
    };
    auto stsA = [&](int st) {
        uint32_t base = sA(st);
        #pragma unroll
        for (int r = 0; r < 4; r++) {
            float4 v = areg[r];
            __half2 h0 = __floats2half2_rn(v.x, v.y);
            __half2 h1 = __floats2half2_rn(v.z, v.w);
            uint32_t u0, u1;
            memcpy(&u0, &h0, 4); memcpy(&u1, &h1, 4);
            asm volatile("st.shared.v2.b32 [%0], {%1, %2};"
                :: "r"(base + ((af_row + r * 32) * BKP + af_col) * 2), "r"(u0), "r"(u1)
                : "memory");
        }
    };

    // prologue: stages 0,1,2
    #pragma unroll
    for (int s = 0; s < 3; s++) {
        cpB(s, s);
        if (CONV) { ldgA(s); stsA(s); } else cpA(s, s);
        cp_commit();
    }

    for (int it = 0; it < NIT; it++) {
        int st = it & 3;
        if (it < NIT - 2) cp_wait2();
        else if (it == NIT - 2) cp_wait1();
        else cp_wait0();
        __syncthreads();
        bool pf = (it + 3 < NIT);
        if (pf) {
            int st2 = (it + 3) & 3;
            cpB(it + 3, st2);
            if (CONV) ldgA(it + 3);
            else cpA(it + 3, st2);
            cp_commit();
        }

        uint32_t a_base = sA(st), b_base = sB(st);
        #pragma unroll
        for (int ks = 0; ks < BK; ks += 16) {
            uint32_t bf[2][4];
            #pragma unroll
            for (int j2 = 0; j2 < 2; j2++)
                ldsm4t(bf[j2], b_base + ((ks + b_r) * BNP + wn + j2 * 16 + b_c) * 2);
            #pragma unroll
            for (int i = 0; i < 4; i++) {
                uint32_t a[4];
                ldsm4(a, a_base + ((wm + i * 16 + a_r) * BKP + ks + a_c) * 2);
                #pragma unroll
                for (int j = 0; j < 4; j++)
                    mma16816(acc[i][j], a, bf[j >> 1][(j & 1) * 2], bf[j >> 1][(j & 1) * 2 + 1]);
            }
        }
        if (pf && CONV) stsA((it + 3) & 3);
    }

    if (FUSE_SCAN) __syncthreads();   // done with stage smem before C-tile reuse
    __half2* Ct = reinterpret_cast<__half2*>(sm);

    // --- store C: gmem for plain/FUSE_E; smem tile only for FUSE_SCAN ---
    #pragma unroll
    for (int i = 0; i < 4; i++) {
        int rl0 = wm + i * 16 + (lane >> 2);
        int r0 = by * BM + rl0;
        int cl0 = wn + (lane & 3) * 2;
        int c0 = bx * BN + cl0;
        #pragma unroll
        for (int j = 0; j < 4; j++) {
            __half2 v0 = __floats2half2_rn(acc[i][j][0], acc[i][j][1]);
            __half2 v1 = __floats2half2_rn(acc[i][j][2], acc[i][j][3]);
            if (FUSE_SCAN) {
                Ct[rl0 * CT_STRIDE + ((cl0 + j * 8) >> 1)] = v0;
                Ct[(rl0 + 8) * CT_STRIDE + ((cl0 + j * 8) >> 1)] = v1;
            } else {
                *reinterpret_cast<__half2*>(&C[(size_t)r0 * 512 + c0 + j * 8]) = v0;
                *reinterpret_cast<__half2*>(&C[(size_t)(r0 + 8) * 512 + c0 + j * 8]) = v1;
            }
        }
    }

    if (FUSE_SCAN) {
        __syncthreads();
        // segment carries over the smem tile (4 segs x 64 p-cols)
        int seg = tid >> 6;
        int pl = tid & 63;
        int pg = bx * 64 + pl;
        {
            float ar = g_lbar[pg], ai = g_lbar[PP + pg];
            float sr = 0.0f, si = 0.0f;
            int t0 = seg * 32;
            #pragma unroll 4
            for (int t = t0; t < t0 + 32; t++) {
                float2 v = __half22float2(Ct[t * CT_STRIDE + pl]);
                float nr = fmaf(ar, sr, fmaf(-ai, si, v.x));
                float ni = fmaf(ar, si, fmaf(ai, sr, v.y));
                sr = nr; si = ni;
            }
            s_part[seg][pl] = make_float2(sr, si);
        }
        __syncthreads();

        int jj = by & (NCHUNK - 1);
        int slot = by * 4 + bx;
        // polite spin: ONE thread polls the predecessor flag with backoff
        if (tid == 0 && jj > 0) {
            volatile int* fl = &g_flag[slot - 4];
            while (*fl == 0) __nanosleep(64);
            __threadfence();
        }
        __syncthreads();
        if (tid < 64) {
            int pg2 = bx * 64 + tid;
            float a32r = g_a32[pg2], a32i = g_a32[PP + pg2];
            float2 c = s_part[0][tid];
            #pragma unroll
            for (int k = 1; k < 4; k++) {
                float2 pk = s_part[k][tid];
                float cr = a32r * c.x - a32i * c.y + pk.x;
                float ci = a32r * c.y + a32i * c.x + pk.y;
                c.x = cr; c.y = ci;
            }
            float2 prev = make_float2(0.0f, 0.0f);
            if (jj > 0) {
                volatile float* ip = &g_incl[(size_t)(slot - 4) * 128 + tid * 2];
                prev.x = ip[0];
                prev.y = ip[1];
            }
            s_seed[tid] = prev;
            float a128r = g_aC[pg2], a128i = g_aC[PP + pg2];
            float ir = a128r * prev.x - a128i * prev.y + c.x;
            float ii = a128r * prev.y + a128i * prev.x + c.y;
            g_incl[(size_t)slot * 128 + tid * 2]     = ir;
            g_incl[(size_t)slot * 128 + tid * 2 + 1] = ii;
        }
        __syncthreads();
        if (tid == 0) {
            __threadfence();
            atomicExch(&g_flag[slot], 1);
        }

        // apply recurrence seeded with exclusive prefix; write xs directly
        {
            float2 st = s_seed[pl];
            float a32r = g_a32[pg], a32i = g_a32[PP + pg];
            #pragma unroll
            for (int k = 0; k < 3; k++) {
                if (k < seg) {
                    float2 pk = s_part[k][pl];
                    float nr = a32r * st.x - a32i * st.y + pk.x;
                    float ni = a32r * st.y + a32i * st.x + pk.y;
                    st.x = nr; st.y = ni;
                }
            }
            float lr = g_lbar[pg], li = g_lbar[PP + pg];
            __half2* xs = reinterpret_cast<__half2*>(C);
            size_t base = (size_t)by * BM * PP + pg;
            int t0 = seg * 32;
            #pragma unroll 4
            for (int t = t0; t < t0 + 32; t++) {
                float2 v = __half22float2(Ct[t * CT_STRIDE + pl]);
                float nr = fmaf(lr, st.x, fmaf(-li, st.y, v.x));
                float ni = fmaf(lr, st.y, fmaf(li, st.x, v.y));
                st.x = nr; st.y = ni;
                xs[base + (size_t)t * PP] = __floats2half2_rn(st.x, st.y);
            }
        }
    }

    if (FUSE_E) {
        // last CTA of this 128-row block runs the full epilogue (L2-hot ys)
        __threadfence();
        if (tid == 0) s_go = (atomicAdd(&g_cnt[by], 1) == 3) ? 1 : 0;
        __syncthreads();
        if (s_go) {
            for (int r = wid; r < BM; r += 8) {
                int row = by * BM + r;
                const __half* ysr = C + (size_t)row * 512;
                const float* xr = Xf + (size_t)row * 512;
                float zv[16];
                float sum = 0.0f, sum2 = 0.0f;
                #pragma unroll
                for (int q = 0; q < 16; q++) {
                    int cc = lane + 32 * q;
                    float ys = __half2float(ysr[cc]);
                    float xv = xr[cc];
                    float y = ys + xv * Dv[cc];
                    float y3 = y * y * y;
                    float u = 0.7978845608028654f * (y + 0.044715f * y3);
                    float g = 0.5f * y * (1.0f + tanhf(u));
                    float z = xv + g;
                    zv[q] = z;
                    sum += z; sum2 += z * z;
                }
                #pragma unroll
                for (int off = 16; off > 0; off >>= 1) {
                    sum  += __shfl_xor_sync(0xFFFFFFFFu, sum, off);
                    sum2 += __shfl_xor_sync(0xFFFFFFFFu, sum2, off);
                }
                float mean = sum * (1.0f / HH);
                float var = sum2 * (1.0f / HH) - mean * mean;
                float rstd = rsqrtf(var + LN_EPS);
                float* outr = out + (size_t)row * 512;
                #pragma unroll
                for (int q = 0; q < 16; q++) {
                    int cc = lane + 32 * q;
                    outr[cc] = (zv[q] - mean) * rstd * ln_scale[cc] + ln_bias[cc];
                }
            }
        }
    }
}

// ---------------------------------------------------------------------------
// Launch
// ---------------------------------------------------------------------------
extern "C" void kernel_launch(void* const* d_in, const int* in_sizes, int n_in,
                              void* d_out, int out_size) {
    const float* x             = (const float*)d_in[0];
    const float* log_lambda_re = (const float*)d_in[1];
    const float* lambda_im     = (const float*)d_in[2];
    const float* B_re          = (const float*)d_in[3];
    const float* B_im          = (const float*)d_in[4];
    const float* C_re          = (const float*)d_in[5];
    const float* C_im          = (const float*)d_in[6];
    const float* D             = (const float*)d_in[7];
    const float* log_step      = (const float*)d_in[8];
    const float* ln_scale      = (const float*)d_in[9];
    const float* ln_bias       = (const float*)d_in[10];
    float* out = (float*)d_out;

    k_setup_all<<<1 + (PP * HH + 255) / 256, 256>>>(
        log_lambda_re, lambda_im, log_step, B_re, B_im, C_re, C_im);

    __half *gXS, *gYS, *gW1, *gW2;
    cudaGetSymbolAddress((void**)&gXS, g_XS);
    cudaGetSymbolAddress((void**)&gYS, g_ysh);
    cudaGetSymbolAddress((void**)&gW1, g_W1);
    cudaGetSymbolAddress((void**)&gW2, g_W2);

    dim3 grid(HH / BN, MM / BM);   // (4, 512)

    // GEMM1: xs = scan(x @ W1) — fused lookback scan (wave-spread chains)
    k_gemm_f16<true, true, false><<<grid, 256>>>(
        x, nullptr, gW1, gXS, nullptr, nullptr, nullptr, nullptr, nullptr);

    // GEMM2: ys = xs @ W2 + fused LN epilogue
    k_gemm_f16<false, false, true><<<grid, 256>>>(
        nullptr, gXS, gW2, gYS, x, D, ln_scale, ln_bias, out);
}